// round 12
// baseline (speedup 1.0000x reference)
#include <cuda_runtime.h>
#include <cuda_fp16.h>
#include <stdint.h>

// Problem constants: B=S=H=DH=64, D = H*DH = 4096
static const int DFEAT = 4096;
static const int NTOK  = 4096;

// GEMM tiling: BM=128, BN=64, BK=64 fp16, warp tile 64x32 (4 warps),
// 4-stage cp.async pipeline, 2 CTAs/SM
static const int BK   = 64;
static const int NKT  = DFEAT / BK;              // 64
static const int A_TILE = 128 * 128;             // 16KB (128 rows x 64 fp16)
static const int B_TILE = 64 * 128;              // 8KB  (64 rows x 64 fp16)
static const int STAGE_BYTES = A_TILE + B_TILE;  // 24KB
static const int NSTAGE      = 4;
static const int SMEM_BYTES  = NSTAGE * STAGE_BYTES;  // 96KB

// Scratch (static device arrays; no allocation allowed)
__device__ float  g_qkv[3ull * (size_t)NTOK * DFEAT];
__device__ __half g_xh[(size_t)NTOK * DFEAT];
__device__ __half g_wh[4ull * (size_t)DFEAT * DFEAT];
__device__ __half g_mh[(size_t)NTOK * DFEAT];

struct GArgs {
    const __half* A;
    const __half* B[3];
    const float*  bias[3];
    float*        C[3];
};
struct CastArgs {
    const float* src[5];
    __half*      dst[5];
};

// ---------------- helpers ----------------
__device__ __forceinline__ uint32_t smem_u32(const void* p) {
    uint32_t a;
    asm("{ .reg .u64 t; cvta.to.shared.u64 t, %1; cvt.u32.u64 %0, t; }" : "=r"(a) : "l"(p));
    return a;
}
__device__ __forceinline__ void cp16(uint32_t dst, const void* src) {
    asm volatile("cp.async.cg.shared.global [%0], [%1], 16;" :: "r"(dst), "l"(src) : "memory");
}
__device__ __forceinline__ void cp_commit() {
    asm volatile("cp.async.commit_group;" ::: "memory");
}
template <int N>
__device__ __forceinline__ void cp_wait() {
    asm volatile("cp.async.wait_group %0;" :: "n"(N) : "memory");
}
__device__ __forceinline__ void ldsm4(uint32_t* r, uint32_t a) {
    asm volatile("ldmatrix.sync.aligned.m8n8.x4.shared.b16 {%0,%1,%2,%3}, [%4];"
                 : "=r"(r[0]), "=r"(r[1]), "=r"(r[2]), "=r"(r[3]) : "r"(a));
}
__device__ __forceinline__ void mma_f16(float c[4], const uint32_t a[4], const uint32_t b[2]) {
    asm volatile(
        "mma.sync.aligned.m16n8k16.row.col.f32.f16.f16.f32 "
        "{%0,%1,%2,%3}, {%4,%5,%6,%7}, {%8,%9}, {%0,%1,%2,%3};\n"
        : "+f"(c[0]), "+f"(c[1]), "+f"(c[2]), "+f"(c[3])
        : "r"(a[0]), "r"(a[1]), "r"(a[2]), "r"(a[3]), "r"(b[0]), "r"(b[1]));
}
// fp32x4 -> fp16 hi/lo pairs, 8B stores to (swizzled) smem
__device__ __forceinline__ void split_sts(uint32_t hi_addr, uint32_t lo_addr, float4 v) {
    __half h0 = __float2half_rn(v.x);
    __half h1 = __float2half_rn(v.y);
    __half h2 = __float2half_rn(v.z);
    __half h3 = __float2half_rn(v.w);
    __half l0 = __float2half_rn(v.x - __half2float(h0));
    __half l1 = __float2half_rn(v.y - __half2float(h1));
    __half l2 = __float2half_rn(v.z - __half2float(h2));
    __half l3 = __float2half_rn(v.w - __half2float(h3));
    uint32_t hA = (uint32_t)__half_as_ushort(h0) | ((uint32_t)__half_as_ushort(h1) << 16);
    uint32_t hB = (uint32_t)__half_as_ushort(h2) | ((uint32_t)__half_as_ushort(h3) << 16);
    uint32_t lA = (uint32_t)__half_as_ushort(l0) | ((uint32_t)__half_as_ushort(l1) << 16);
    uint32_t lB = (uint32_t)__half_as_ushort(l2) | ((uint32_t)__half_as_ushort(l3) << 16);
    asm volatile("st.shared.v2.b32 [%0], {%1,%2};" :: "r"(hi_addr), "r"(hA), "r"(hB) : "memory");
    asm volatile("st.shared.v2.b32 [%0], {%1,%2};" :: "r"(lo_addr), "r"(lA), "r"(lB) : "memory");
}

// ---------------- fused fp32 -> fp16 casts (5 equal-size tensors) ----------------
__global__ __launch_bounds__(256) void cast5_kernel(CastArgs a, int n4) {
    const int z = blockIdx.z;
    const float4* s4 = (const float4*)a.src[z];
    uint2* d2 = (uint2*)a.dst[z];
    int i = blockIdx.x * blockDim.x + threadIdx.x;
    const int stride = gridDim.x * blockDim.x;
    for (; i < n4; i += stride) {
        float4 v = s4[i];
        __half2 p0 = __floats2half2_rn(v.x, v.y);
        __half2 p1 = __floats2half2_rn(v.z, v.w);
        uint2 o;
        o.x = *(const uint32_t*)&p0;
        o.y = *(const uint32_t*)&p1;
        d2[i] = o;
    }
}

// ---------------- fp16 HMMA GEMM ----------------
// C[m][n] = sum_k A[m][k]*B[n][k] + bias[n]
// 128 threads, warp grid 2(M) x 2(N), warp tile 64x32, BM=128, BN=64, BK=64.
// 4-stage cp.async pipeline, 2 CTAs/SM. Fine tiles minimize wave-tail waste.
__global__ __launch_bounds__(128, 2) void gemm_hmma(GArgs g) {
    extern __shared__ __align__(1024) char smem[];
    const int z = blockIdx.z;
    const __half* __restrict__ A = g.A;
    const __half* __restrict__ B = g.B[z];
    const float* __restrict__ bias = g.bias[z];
    float* __restrict__ C = g.C[z];

    const int tid  = threadIdx.x;
    const int lane = tid & 31;
    const int wid  = tid >> 5;
    const int wm = (wid & 1) * 64;           // 2 warps along M
    const int wn = (wid >> 1) * 32;          // 2 warps along N
    const int m0 = blockIdx.y * 128;
    const int n0 = blockIdx.x * 64;
    const uint32_t sb = smem_u32(smem);

    // ---- loader mapping ----
    // A: 128 rows x 8 chunk16 = 1024 ids -> 8 per thread
    uint32_t dA[8]; int gA[8];
    #pragma unroll
    for (int i = 0; i < 8; ++i) {
        const int id = tid + i * 128;
        const int r  = id >> 3;
        const int c  = id & 7;
        dA[i] = (uint32_t)(r * 128 + ((c ^ (r & 7)) << 4));
        gA[i] = r * DFEAT + c * 8;
    }
    // B: 64 rows x 8 chunk16 = 512 ids -> 4 per thread
    uint32_t dB[4]; int gB[4];
    #pragma unroll
    for (int i = 0; i < 4; ++i) {
        const int id = tid + i * 128;
        const int r  = id >> 3;
        const int c  = id & 7;
        dB[i] = (uint32_t)(r * 128 + ((c ^ (r & 7)) << 4));
        gB[i] = r * DFEAT + c * 8;
    }
    const __half* pA = A + (size_t)m0 * DFEAT;
    const __half* pB = B + (size_t)n0 * DFEAT;

    // ---- ldmatrix lane mapping ----
    uint32_t aoff[4], amask[4];
    const int asel = lane >> 4;
    #pragma unroll
    for (int mt = 0; mt < 4; ++mt) {
        const int rowA = wm + mt * 16 + (((lane >> 3) & 1) << 3) + (lane & 7);
        aoff[mt]  = (uint32_t)(rowA * 128);
        amask[mt] = (uint32_t)((rowA & 7) << 4);
    }
    uint32_t boff[2], bmask[2];
    const int bsel = (lane >> 3) & 1;
    #pragma unroll
    for (int p = 0; p < 2; ++p) {
        const int nrow = wn + p * 16 + ((lane >> 4) << 3) + (lane & 7);
        boff[p]  = (uint32_t)(nrow * 128);
        bmask[p] = (uint32_t)((nrow & 7) << 4);
    }

    float acc[4][4][4];
    #pragma unroll
    for (int a = 0; a < 4; ++a)
        #pragma unroll
        for (int b = 0; b < 4; ++b)
            #pragma unroll
            for (int c = 0; c < 4; ++c) acc[a][b][c] = 0.0f;

    // ---- prologue: fill 3 of 4 stages ----
    #pragma unroll
    for (int s = 0; s < 3; ++s) {
        const uint32_t st = sb + s * STAGE_BYTES;
        const int ko = s * BK;
        #pragma unroll
        for (int i = 0; i < 8; ++i) cp16(st + dA[i], pA + gA[i] + ko);
        #pragma unroll
        for (int i = 0; i < 4; ++i) cp16(st + A_TILE + dB[i], pB + gB[i] + ko);
        cp_commit();
    }

    for (int kt = 0; kt < NKT; ++kt) {
        if (kt < NKT - 2)       cp_wait<2>();
        else if (kt == NKT - 2) cp_wait<1>();
        else                    cp_wait<0>();
        __syncthreads();

        // prefetch stage kt+3 into slot (kt+3)%4 (= slot consumed at iter kt-1)
        if (kt + 3 < NKT) {
            const uint32_t stn = sb + ((kt + 3) % NSTAGE) * STAGE_BYTES;
            const int ko = (kt + 3) * BK;
            #pragma unroll
            for (int i = 0; i < 8; ++i) cp16(stn + dA[i], pA + gA[i] + ko);
            #pragma unroll
            for (int i = 0; i < 4; ++i) cp16(stn + A_TILE + dB[i], pB + gB[i] + ko);
            cp_commit();
        }

        const uint32_t st  = sb + (kt % NSTAGE) * STAGE_BYTES;
        const uint32_t stA = st;
        const uint32_t stB = st + A_TILE;

        #pragma unroll
        for (int k16 = 0; k16 < 4; ++k16) {
            const uint32_t ka = (uint32_t)((2 * k16 + asel) << 4);
            const uint32_t kb = (uint32_t)((2 * k16 + bsel) << 4);
            uint32_t ah[4][4], bh[2][4];
            #pragma unroll
            for (int mt = 0; mt < 4; ++mt)
                ldsm4(ah[mt], stA + aoff[mt] + (ka ^ amask[mt]));
            #pragma unroll
            for (int p = 0; p < 2; ++p)
                ldsm4(bh[p], stB + boff[p] + (kb ^ bmask[p]));
            #pragma unroll
            for (int mt = 0; mt < 4; ++mt) {
                #pragma unroll
                for (int nt = 0; nt < 4; ++nt) {
                    const int p = nt >> 1;
                    const int h = (nt & 1) * 2;
                    mma_f16(acc[mt][nt], ah[mt], &bh[p][h]);
                }
            }
        }
    }

    // ---- epilogue: bias + fp32 store ----
    #pragma unroll
    for (int mt = 0; mt < 4; ++mt) {
        const int row = m0 + wm + mt * 16 + (lane >> 2);
        #pragma unroll
        for (int nt = 0; nt < 4; ++nt) {
            const int col = n0 + wn + nt * 8 + (lane & 3) * 2;
            const float2 bb = *(const float2*)&bias[col];
            *(float2*)&C[(size_t)row * DFEAT + col] =
                make_float2(acc[mt][nt][0] + bb.x, acc[mt][nt][1] + bb.y);
            *(float2*)&C[(size_t)(row + 8) * DFEAT + col] =
                make_float2(acc[mt][nt][2] + bb.x, acc[mt][nt][3] + bb.y);
        }
    }
}

// ---------------- per-token attention via fp16x2 HMMA (unchanged from R10) ----------------
__global__ __launch_bounds__(128) void attn_hmma(const float* __restrict__ qkv,
                                                 __half* __restrict__ mh) {
    __shared__ __align__(1024) char smem[6 * 8192];  // qh ql kh kl vh vl
    const int m = blockIdx.x;
    const int b = m >> 6;
    const int s = m & 63;
    const int tid  = threadIdx.x;
    const int lane = tid & 31;
    const int w    = tid >> 5;
    const uint32_t sb = smem_u32(smem);

    const float* Qp = qkv + (size_t)m * DFEAT;
    #pragma unroll
    for (int t = 0; t < 3; ++t) {
        const float* src = Qp + (size_t)t * NTOK * DFEAT;
        const uint32_t hbase = sb + (uint32_t)(2 * t) * 8192u;
        const uint32_t lbase = hbase + 8192u;
        #pragma unroll
        for (int i = 0; i < 8; ++i) {
            const int id  = tid + i * 128;
            const int row = id >> 4;
            const int c4  = id & 15;
            float4 v = *(const float4*)(src + row * 64 + c4 * 4);
            const uint32_t off =
                (uint32_t)(row * 128 + (((c4 >> 1) ^ (row & 7)) << 4) + (c4 & 1) * 8);
            split_sts(hbase + off, lbase + off, v);
        }
    }
    __syncthreads();

    const uint32_t SQH = sb, SQL = sb + 8192, SKH = sb + 16384, SKL = sb + 24576,
                   SVH = sb + 32768, SVL = sb + 40960;

    const int tg = lane & 3;
    const int rowA = w * 16 + (((lane >> 3) & 1) << 3) + (lane & 7);
    const uint32_t aoff  = (uint32_t)(rowA * 128);
    const uint32_t amask = (uint32_t)((rowA & 7) << 4);
    const int asel = lane >> 4;
    uint32_t boff[4], bmask[4];
    const int bsel = (lane >> 3) & 1;
    #pragma unroll
    for (int p = 0; p < 4; ++p) {
        const int nrow = p * 16 + ((lane >> 4) << 3) + (lane & 7);
        boff[p]  = (uint32_t)(nrow * 128);
        bmask[p] = (uint32_t)((nrow & 7) << 4);
    }

    float acc[8][4];
    #pragma unroll
    for (int nt = 0; nt < 8; ++nt)
        #pragma unroll
        for (int j = 0; j < 4; ++j) acc[nt][j] = 0.0f;

    #pragma unroll
    for (int k16 = 0; k16 < 4; ++k16) {
        const uint32_t ka = (uint32_t)((2 * k16 + asel) << 4);
        const uint32_t kb = (uint32_t)((2 * k16 + bsel) << 4);
        uint32_t ah[4], al[4], bh[4][4], bl[4][4];
        ldsm4(ah, SQH + aoff + (ka ^ amask));
        ldsm4(al, SQL + aoff + (ka ^ amask));
        #pragma unroll
        for (int p = 0; p < 4; ++p) {
            ldsm4(bh[p], SKH + boff[p] + (kb ^ bmask[p]));
            ldsm4(bl[p], SKL + boff[p] + (kb ^ bmask[p]));
        }
        #pragma unroll
        for (int nt = 0; nt < 8; ++nt) {
            const int p = nt >> 1;
            const int h = (nt & 1) * 2;
            mma_f16(acc[nt], ah, &bh[p][h]);
            mma_f16(acc[nt], ah, &bl[p][h]);
            mma_f16(acc[nt], al, &bh[p][h]);
        }
    }

    #pragma unroll
    for (int hf = 0; hf < 2; ++hf) {
        const int o = hf * 2;
        float mx = -1e30f;
        #pragma unroll
        for (int nt = 0; nt < 8; ++nt) {
            acc[nt][o]     *= 0.125f;
            acc[nt][o + 1] *= 0.125f;
            mx = fmaxf(mx, fmaxf(acc[nt][o], acc[nt][o + 1]));
        }
        mx = fmaxf(mx, __shfl_xor_sync(0xffffffffu, mx, 1));
        mx = fmaxf(mx, __shfl_xor_sync(0xffffffffu, mx, 2));
        float sum = 0.0f;
        #pragma unroll
        for (int nt = 0; nt < 8; ++nt) {
            float e0 = __expf(acc[nt][o] - mx);
            float e1 = __expf(acc[nt][o + 1] - mx);
            acc[nt][o] = e0;
            acc[nt][o + 1] = e1;
            sum += e0 + e1;
        }
        sum += __shfl_xor_sync(0xffffffffu, sum, 1);
        sum += __shfl_xor_sync(0xffffffffu, sum, 2);
        const float inv = 1.0f / sum;
        #pragma unroll
        for (int nt = 0; nt < 8; ++nt) {
            acc[nt][o]     *= inv;
            acc[nt][o + 1] *= inv;
        }
    }

    uint32_t pah[4][4], pal[4][4];
    #pragma unroll
    for (int kk = 0; kk < 4; ++kk) {
        #pragma unroll
        for (int r = 0; r < 4; ++r) {
            const int nt = 2 * kk + (r >> 1);
            const int o  = (r & 1) * 2;
            const float x = acc[nt][o];
            const float y = acc[nt][o + 1];
            const __half hx = __float2half_rn(x);
            const __half hy = __float2half_rn(y);
            const __half lx = __float2half_rn(x - __half2float(hx));
            const __half ly = __float2half_rn(y - __half2float(hy));
            pah[kk][r] = (uint32_t)__half_as_ushort(hx) | ((uint32_t)__half_as_ushort(hy) << 16);
            pal[kk][r] = (uint32_t)__half_as_ushort(lx) | ((uint32_t)__half_as_ushort(ly) << 16);
        }
    }

    #pragma unroll
    for (int nt = 0; nt < 8; ++nt)
        #pragma unroll
        for (int j = 0; j < 4; ++j) acc[nt][j] = 0.0f;

    #pragma unroll
    for (int k16 = 0; k16 < 4; ++k16) {
        const uint32_t kb = (uint32_t)((2 * k16 + bsel) << 4);
        uint32_t vh[4][4], vl[4][4];
        #pragma unroll
        for (int p = 0; p < 4; ++p) {
            ldsm4(vh[p], SVH + boff[p] + (kb ^ bmask[p]));
            ldsm4(vl[p], SVL + boff[p] + (kb ^ bmask[p]));
        }
        #pragma unroll
        for (int nt = 0; nt < 8; ++nt) {
            const int p = nt >> 1;
            const int h = (nt & 1) * 2;
            mma_f16(acc[nt], pah[k16], &vh[p][h]);
            mma_f16(acc[nt], pah[k16], &vl[p][h]);
            mma_f16(acc[nt], pal[k16], &vh[p][h]);
        }
    }

    const int row0 = w * 16 + (lane >> 2);
    #pragma unroll
    for (int nt = 0; nt < 8; ++nt) {
        const int col = nt * 8 + tg * 2;
        __half2 v0 = __floats2half2_rn(acc[nt][0], acc[nt][1]);
        __half2 v1 = __floats2half2_rn(acc[nt][2], acc[nt][3]);
        *(__half2*)&mh[(size_t)(b * 64 + row0) * DFEAT + s * 64 + col] = v0;
        *(__half2*)&mh[(size_t)(b * 64 + row0 + 8) * DFEAT + s * 64 + col] = v1;
    }
}

extern "C" void kernel_launch(void* const* d_in, const int* in_sizes, int n_in,
                              void* d_out, int out_size) {
    const float* x  = (const float*)d_in[0];
    const float* Wq = (const float*)d_in[1];
    const float* bq = (const float*)d_in[2];
    const float* Wk = (const float*)d_in[3];
    const float* bk = (const float*)d_in[4];
    const float* Wv = (const float*)d_in[5];
    const float* bv = (const float*)d_in[6];
    const float* Wp = (const float*)d_in[7];
    const float* bp = (const float*)d_in[8];
    float* out = (float*)d_out;

    float* qkv = nullptr;
    __half *xh, *wh, *mh;
    cudaGetSymbolAddress((void**)&qkv, g_qkv);
    cudaGetSymbolAddress((void**)&xh, g_xh);
    cudaGetSymbolAddress((void**)&wh, g_wh);
    cudaGetSymbolAddress((void**)&mh, g_mh);

    cudaFuncSetAttribute(gemm_hmma, cudaFuncAttributeMaxDynamicSharedMemorySize, SMEM_BYTES);

    const size_t MSZ = (size_t)DFEAT * DFEAT;
    const int n4 = (int)(MSZ / 4);

    // 0) fused casts: x + 4 weights
    CastArgs ca;
    ca.src[0] = x;  ca.dst[0] = xh;
    ca.src[1] = Wq; ca.dst[1] = wh;
    ca.src[2] = Wk; ca.dst[2] = wh + MSZ;
    ca.src[3] = Wv; ca.dst[3] = wh + 2 * MSZ;
    ca.src[4] = Wp; ca.dst[4] = wh + 3 * MSZ;
    cast5_kernel<<<dim3(512, 1, 5), 256>>>(ca, n4);

    // 1) QKV projections (BN=64 tiles: fine-grained waves)
    GArgs a1;
    a1.A = xh;
    a1.B[0] = wh;
    a1.B[1] = wh + MSZ;
    a1.B[2] = wh + 2 * MSZ;
    a1.bias[0] = bq; a1.bias[1] = bk; a1.bias[2] = bv;
    a1.C[0] = qkv;
    a1.C[1] = qkv + (size_t)NTOK * DFEAT;
    a1.C[2] = qkv + 2ull * NTOK * DFEAT;
    gemm_hmma<<<dim3(64, 32, 3), 128, SMEM_BYTES>>>(a1);

    // 2) per-token attention -> merged (fp16), tensor-core path
    attn_hmma<<<NTOK, 128>>>(qkv, mh);

    // 3) output projection
    GArgs a2;
    a2.A = mh;
    a2.B[0] = wh + 3 * MSZ;
    a2.B[1] = a2.B[0];
    a2.B[2] = a2.B[0];
    a2.bias[0] = bp; a2.bias[1] = bp; a2.bias[2] = bp;
    a2.C[0] = out; a2.C[1] = out; a2.C[2] = out;
    gemm_hmma<<<dim3(64, 32, 1), 128, SMEM_BYTES>>>(a2);
}

// round 14
// speedup vs baseline: 1.0601x; 1.0601x over previous
#include <cuda_runtime.h>
#include <cuda_fp16.h>
#include <stdint.h>

// Problem constants: B=S=H=DH=64, D = H*DH = 4096
static const int DFEAT = 4096;
static const int NTOK  = 4096;

// GEMM: BM=BN=128, BK=128 per stage, 3 stages, warp-specialized (8 cons + 4 prod warps)
static const int BKS   = 128;                    // k per stage
static const int NKT   = DFEAT / BKS;            // 32
static const int HALF_TILE = 128 * 128;          // 16KB: 128 rows x 64 fp16 (one k-half)
static const int STAGE_BYTES = 4 * HALF_TILE;    // A0,A1,B0,B1 = 64KB
static const int NSTAGE = 3;
static const int MB_BYTES = 64;
static const int SMEM_BYTES = NSTAGE * STAGE_BYTES + MB_BYTES;  // 196672

// Scratch (static device arrays; no allocation allowed)
__device__ float  g_qkv[3ull * (size_t)NTOK * DFEAT];
__device__ __half g_xh[(size_t)NTOK * DFEAT];
__device__ __half g_wh[4ull * (size_t)DFEAT * DFEAT];
__device__ __half g_mh[(size_t)NTOK * DFEAT];

struct GArgs {
    const __half* A;
    const __half* B[3];
    const float*  bias[3];
    float*        C[3];
};
struct CastArgs {
    const float* src[5];
    __half*      dst[5];
};

// ---------------- helpers ----------------
__device__ __forceinline__ uint32_t smem_u32(const void* p) {
    uint32_t a;
    asm("{ .reg .u64 t; cvta.to.shared.u64 t, %1; cvt.u32.u64 %0, t; }" : "=r"(a) : "l"(p));
    return a;
}
__device__ __forceinline__ void cp16(uint32_t dst, const void* src) {
    asm volatile("cp.async.cg.shared.global [%0], [%1], 16;" :: "r"(dst), "l"(src) : "memory");
}
__device__ __forceinline__ void ldsm4(uint32_t* r, uint32_t a) {
    asm volatile("ldmatrix.sync.aligned.m8n8.x4.shared.b16 {%0,%1,%2,%3}, [%4];"
                 : "=r"(r[0]), "=r"(r[1]), "=r"(r[2]), "=r"(r[3]) : "r"(a));
}
__device__ __forceinline__ void mma_f16(float c[4], const uint32_t a[4], const uint32_t b[2]) {
    asm volatile(
        "mma.sync.aligned.m16n8k16.row.col.f32.f16.f16.f32 "
        "{%0,%1,%2,%3}, {%4,%5,%6,%7}, {%8,%9}, {%0,%1,%2,%3};\n"
        : "+f"(c[0]), "+f"(c[1]), "+f"(c[2]), "+f"(c[3])
        : "r"(a[0]), "r"(a[1]), "r"(a[2]), "r"(a[3]), "r"(b[0]), "r"(b[1]));
}
__device__ __forceinline__ void mbar_init(uint32_t mbar, uint32_t cnt) {
    asm volatile("mbarrier.init.shared.b64 [%0], %1;" :: "r"(mbar), "r"(cnt) : "memory");
}
__device__ __forceinline__ void mbar_wait(uint32_t mbar, uint32_t parity) {
    asm volatile(
        "{\n\t.reg .pred P;\n\t"
        "WL_%=:\n\t"
        "mbarrier.try_wait.parity.acquire.cta.shared::cta.b64 P, [%0], %1, 0x989680;\n\t"
        "@P bra WD_%=;\n\t"
        "bra WL_%=;\n\t"
        "WD_%=:\n\t}"
        :: "r"(mbar), "r"(parity) : "memory");
}
__device__ __forceinline__ void mbar_arrive(uint32_t mbar) {
    asm volatile("mbarrier.arrive.shared.b64 _, [%0];" :: "r"(mbar) : "memory");
}
// .noinc: do NOT bump pending count at issue — init count covers the 128
// producer-thread async arrivals. (Default form self-increments and deadlocks.)
__device__ __forceinline__ void cp_async_arrive(uint32_t mbar) {
    asm volatile("cp.async.mbarrier.arrive.noinc.shared.b64 [%0];" :: "r"(mbar) : "memory");
}
// fp32x4 -> fp16 hi/lo pairs, 8B stores to (swizzled) smem
__device__ __forceinline__ void split_sts(uint32_t hi_addr, uint32_t lo_addr, float4 v) {
    __half h0 = __float2half_rn(v.x);
    __half h1 = __float2half_rn(v.y);
    __half h2 = __float2half_rn(v.z);
    __half h3 = __float2half_rn(v.w);
    __half l0 = __float2half_rn(v.x - __half2float(h0));
    __half l1 = __float2half_rn(v.y - __half2float(h1));
    __half l2 = __float2half_rn(v.z - __half2float(h2));
    __half l3 = __float2half_rn(v.w - __half2float(h3));
    uint32_t hA = (uint32_t)__half_as_ushort(h0) | ((uint32_t)__half_as_ushort(h1) << 16);
    uint32_t hB = (uint32_t)__half_as_ushort(h2) | ((uint32_t)__half_as_ushort(h3) << 16);
    uint32_t lA = (uint32_t)__half_as_ushort(l0) | ((uint32_t)__half_as_ushort(l1) << 16);
    uint32_t lB = (uint32_t)__half_as_ushort(l2) | ((uint32_t)__half_as_ushort(l3) << 16);
    asm volatile("st.shared.v2.b32 [%0], {%1,%2};" :: "r"(hi_addr), "r"(hA), "r"(hB) : "memory");
    asm volatile("st.shared.v2.b32 [%0], {%1,%2};" :: "r"(lo_addr), "r"(lA), "r"(lB) : "memory");
}

// ---------------- fused fp32 -> fp16 casts (5 equal-size tensors) ----------------
__global__ __launch_bounds__(256) void cast5_kernel(CastArgs a, int n4) {
    const int z = blockIdx.z;
    const float4* s4 = (const float4*)a.src[z];
    uint2* d2 = (uint2*)a.dst[z];
    int i = blockIdx.x * blockDim.x + threadIdx.x;
    const int stride = gridDim.x * blockDim.x;
    for (; i < n4; i += stride) {
        float4 v = s4[i];
        __half2 p0 = __floats2half2_rn(v.x, v.y);
        __half2 p1 = __floats2half2_rn(v.z, v.w);
        uint2 o;
        o.x = *(const uint32_t*)&p0;
        o.y = *(const uint32_t*)&p1;
        d2[i] = o;
    }
}

// ---------------- warp-specialized fp16 HMMA GEMM ----------------
// C[m][n] = sum_k A[m][k]*B[n][k] + bias[n]
// 384 threads: warps 0-7 consumers (2Mx4N grid, warp tile 64x32),
// warps 8-11 producers (cp.async). mbarrier full/empty handshake, no bar.sync
// in the mainloop. BM=BN=128, BK=128/stage, 3 stages.
__global__ __launch_bounds__(384, 1) void gemm_hmma(GArgs g) {
    extern __shared__ __align__(1024) char smem[];
    const int z = blockIdx.z;
    const __half* __restrict__ A = g.A;
    const __half* __restrict__ B = g.B[z];
    const float* __restrict__ bias = g.bias[z];
    float* __restrict__ C = g.C[z];

    const int tid  = threadIdx.x;
    const int lane = tid & 31;
    const int wid  = tid >> 5;
    const int m0 = blockIdx.y * 128;
    const int n0 = blockIdx.x * 128;
    const uint32_t sb = smem_u32(smem);
    const uint32_t mb = sb + (uint32_t)(NSTAGE * STAGE_BYTES);
    // full[s] = mb + 16s, empty[s] = mb + 16s + 8

    if (tid == 0) {
        #pragma unroll
        for (int s = 0; s < NSTAGE; ++s) {
            mbar_init(mb + 16 * s, 128);     // full: 128 producer-thread async arrivals
            mbar_init(mb + 16 * s + 8, 8);   // empty: 8 consumer-warp arrivals
        }
    }
    __syncthreads();

    if (wid >= 8) {
        // ================= producer =================
        const int pt = tid - 256;  // 0..127
        uint32_t dA[16]; int gA[16];
        #pragma unroll
        for (int i = 0; i < 16; ++i) {
            const int id   = pt + i * 128;       // 0..2047
            const int half = id >> 10;           // k-half
            const int w10  = id & 1023;
            const int r    = w10 >> 3;           // row 0..127
            const int c    = w10 & 7;            // chunk16
            dA[i] = (uint32_t)(half * HALF_TILE + r * 128 + ((c ^ (r & 7)) << 4));
            gA[i] = r * DFEAT + half * 64 + c * 8;
        }
        const __half* pA = A + (size_t)m0 * DFEAT;
        const __half* pB = B + (size_t)n0 * DFEAT;

        uint32_t pph = 0x7;  // per-stage parity, producers start flipped
        for (int kt = 0; kt < NKT; ++kt) {
            const int s = kt % NSTAGE;
            mbar_wait(mb + 16 * s + 8, (pph >> s) & 1);
            pph ^= (1u << s);
            const uint32_t st = sb + (uint32_t)s * STAGE_BYTES;
            const int ko = kt * BKS;
            #pragma unroll
            for (int i = 0; i < 16; ++i) {
                cp16(st + dA[i],                 pA + gA[i] + ko);
                cp16(st + 2 * HALF_TILE + dA[i], pB + gA[i] + ko);
            }
            cp_async_arrive(mb + 16 * s);
        }
        return;
    }

    // ================= consumer =================
    const int wm = (wid & 1) * 64;
    const int wn = (wid >> 1) * 32;

    uint32_t aoff[4], amask[4];
    const int asel = lane >> 4;
    #pragma unroll
    for (int mt = 0; mt < 4; ++mt) {
        const int rowA = wm + mt * 16 + (((lane >> 3) & 1) << 3) + (lane & 7);
        aoff[mt]  = (uint32_t)(rowA * 128);
        amask[mt] = (uint32_t)((rowA & 7) << 4);
    }
    uint32_t boff[2], bmask[2];
    const int bsel = (lane >> 3) & 1;
    #pragma unroll
    for (int p = 0; p < 2; ++p) {
        const int nrow = wn + p * 16 + ((lane >> 4) << 3) + (lane & 7);
        boff[p]  = (uint32_t)(nrow * 128);
        bmask[p] = (uint32_t)((nrow & 7) << 4);
    }

    float acc[4][4][4];
    #pragma unroll
    for (int a = 0; a < 4; ++a)
        #pragma unroll
        for (int b = 0; b < 4; ++b)
            #pragma unroll
            for (int c = 0; c < 4; ++c) acc[a][b][c] = 0.0f;

    uint32_t fph = 0;
    for (int kt = 0; kt < NKT; ++kt) {
        const int s = kt % NSTAGE;
        mbar_wait(mb + 16 * s, (fph >> s) & 1);
        fph ^= (1u << s);
        const uint32_t st = sb + (uint32_t)s * STAGE_BYTES;

        #pragma unroll
        for (int k16 = 0; k16 < 8; ++k16) {
            const int half = k16 >> 2;
            const int kk   = k16 & 3;
            const uint32_t stA = st + (uint32_t)half * HALF_TILE;
            const uint32_t stB = st + 2 * HALF_TILE + (uint32_t)half * HALF_TILE;
            const uint32_t ka = (uint32_t)((2 * kk + asel) << 4);
            const uint32_t kb = (uint32_t)((2 * kk + bsel) << 4);
            uint32_t ah[4][4], bh[2][4];
            #pragma unroll
            for (int mt = 0; mt < 4; ++mt)
                ldsm4(ah[mt], stA + aoff[mt] + (ka ^ amask[mt]));
            #pragma unroll
            for (int p = 0; p < 2; ++p)
                ldsm4(bh[p], stB + boff[p] + (kb ^ bmask[p]));
            #pragma unroll
            for (int mt = 0; mt < 4; ++mt) {
                #pragma unroll
                for (int nt = 0; nt < 4; ++nt) {
                    const int p = nt >> 1;
                    const int h = (nt & 1) * 2;
                    mma_f16(acc[mt][nt], ah[mt], &bh[p][h]);
                }
            }
        }
        if (lane == 0) mbar_arrive(mb + 16 * s + 8);
    }

    // ---- epilogue: bias + fp32 store ----
    #pragma unroll
    for (int mt = 0; mt < 4; ++mt) {
        const int row = m0 + wm + mt * 16 + (lane >> 2);
        #pragma unroll
        for (int nt = 0; nt < 4; ++nt) {
            const int col = n0 + wn + nt * 8 + (lane & 3) * 2;
            const float2 bb = *(const float2*)&bias[col];
            *(float2*)&C[(size_t)row * DFEAT + col] =
                make_float2(acc[mt][nt][0] + bb.x, acc[mt][nt][1] + bb.y);
            *(float2*)&C[(size_t)(row + 8) * DFEAT + col] =
                make_float2(acc[mt][nt][2] + bb.x, acc[mt][nt][3] + bb.y);
        }
    }
}

// ---------------- per-token attention via fp16x2 HMMA (unchanged from R10) ----------------
__global__ __launch_bounds__(128) void attn_hmma(const float* __restrict__ qkv,
                                                 __half* __restrict__ mh) {
    __shared__ __align__(1024) char smem[6 * 8192];  // qh ql kh kl vh vl
    const int m = blockIdx.x;
    const int b = m >> 6;
    const int s = m & 63;
    const int tid  = threadIdx.x;
    const int lane = tid & 31;
    const int w    = tid >> 5;
    const uint32_t sb = smem_u32(smem);

    const float* Qp = qkv + (size_t)m * DFEAT;
    #pragma unroll
    for (int t = 0; t < 3; ++t) {
        const float* src = Qp + (size_t)t * NTOK * DFEAT;
        const uint32_t hbase = sb + (uint32_t)(2 * t) * 8192u;
        const uint32_t lbase = hbase + 8192u;
        #pragma unroll
        for (int i = 0; i < 8; ++i) {
            const int id  = tid + i * 128;
            const int row = id >> 4;
            const int c4  = id & 15;
            float4 v = *(const float4*)(src + row * 64 + c4 * 4);
            const uint32_t off =
                (uint32_t)(row * 128 + (((c4 >> 1) ^ (row & 7)) << 4) + (c4 & 1) * 8);
            split_sts(hbase + off, lbase + off, v);
        }
    }
    __syncthreads();

    const uint32_t SQH = sb, SQL = sb + 8192, SKH = sb + 16384, SKL = sb + 24576,
                   SVH = sb + 32768, SVL = sb + 40960;

    const int tg = lane & 3;
    const int rowA = w * 16 + (((lane >> 3) & 1) << 3) + (lane & 7);
    const uint32_t aoff  = (uint32_t)(rowA * 128);
    const uint32_t amask = (uint32_t)((rowA & 7) << 4);
    const int asel = lane >> 4;
    uint32_t boff[4], bmask[4];
    const int bsel = (lane >> 3) & 1;
    #pragma unroll
    for (int p = 0; p < 4; ++p) {
        const int nrow = p * 16 + ((lane >> 4) << 3) + (lane & 7);
        boff[p]  = (uint32_t)(nrow * 128);
        bmask[p] = (uint32_t)((nrow & 7) << 4);
    }

    float acc[8][4];
    #pragma unroll
    for (int nt = 0; nt < 8; ++nt)
        #pragma unroll
        for (int j = 0; j < 4; ++j) acc[nt][j] = 0.0f;

    #pragma unroll
    for (int k16 = 0; k16 < 4; ++k16) {
        const uint32_t ka = (uint32_t)((2 * k16 + asel) << 4);
        const uint32_t kb = (uint32_t)((2 * k16 + bsel) << 4);
        uint32_t ah[4], al[4], bh[4][4], bl[4][4];
        ldsm4(ah, SQH + aoff + (ka ^ amask));
        ldsm4(al, SQL + aoff + (ka ^ amask));
        #pragma unroll
        for (int p = 0; p < 4; ++p) {
            ldsm4(bh[p], SKH + boff[p] + (kb ^ bmask[p]));
            ldsm4(bl[p], SKL + boff[p] + (kb ^ bmask[p]));
        }
        #pragma unroll
        for (int nt = 0; nt < 8; ++nt) {
            const int p = nt >> 1;
            const int h = (nt & 1) * 2;
            mma_f16(acc[nt], ah, &bh[p][h]);
            mma_f16(acc[nt], ah, &bl[p][h]);
            mma_f16(acc[nt], al, &bh[p][h]);
        }
    }

    #pragma unroll
    for (int hf = 0; hf < 2; ++hf) {
        const int o = hf * 2;
        float mx = -1e30f;
        #pragma unroll
        for (int nt = 0; nt < 8; ++nt) {
            acc[nt][o]     *= 0.125f;
            acc[nt][o + 1] *= 0.125f;
            mx = fmaxf(mx, fmaxf(acc[nt][o], acc[nt][o + 1]));
        }
        mx = fmaxf(mx, __shfl_xor_sync(0xffffffffu, mx, 1));
        mx = fmaxf(mx, __shfl_xor_sync(0xffffffffu, mx, 2));
        float sum = 0.0f;
        #pragma unroll
        for (int nt = 0; nt < 8; ++nt) {
            float e0 = __expf(acc[nt][o] - mx);
            float e1 = __expf(acc[nt][o + 1] - mx);
            acc[nt][o] = e0;
            acc[nt][o + 1] = e1;
            sum += e0 + e1;
        }
        sum += __shfl_xor_sync(0xffffffffu, sum, 1);
        sum += __shfl_xor_sync(0xffffffffu, sum, 2);
        const float inv = 1.0f / sum;
        #pragma unroll
        for (int nt = 0; nt < 8; ++nt) {
            acc[nt][o]     *= inv;
            acc[nt][o + 1] *= inv;
        }
    }

    uint32_t pah[4][4], pal[4][4];
    #pragma unroll
    for (int kk = 0; kk < 4; ++kk) {
        #pragma unroll
        for (int r = 0; r < 4; ++r) {
            const int nt = 2 * kk + (r >> 1);
            const int o  = (r & 1) * 2;
            const float x = acc[nt][o];
            const float y = acc[nt][o + 1];
            const __half hx = __float2half_rn(x);
            const __half hy = __float2half_rn(y);
            const __half lx = __float2half_rn(x - __half2float(hx));
            const __half ly = __float2half_rn(y - __half2float(hy));
            pah[kk][r] = (uint32_t)__half_as_ushort(hx) | ((uint32_t)__half_as_ushort(hy) << 16);
            pal[kk][r] = (uint32_t)__half_as_ushort(lx) | ((uint32_t)__half_as_ushort(ly) << 16);
        }
    }

    #pragma unroll
    for (int nt = 0; nt < 8; ++nt)
        #pragma unroll
        for (int j = 0; j < 4; ++j) acc[nt][j] = 0.0f;

    #pragma unroll
    for (int k16 = 0; k16 < 4; ++k16) {
        const uint32_t kb = (uint32_t)((2 * k16 + bsel) << 4);
        uint32_t vh[4][4], vl[4][4];
        #pragma unroll
        for (int p = 0; p < 4; ++p) {
            ldsm4(vh[p], SVH + boff[p] + (kb ^ bmask[p]));
            ldsm4(vl[p], SVL + boff[p] + (kb ^ bmask[p]));
        }
        #pragma unroll
        for (int nt = 0; nt < 8; ++nt) {
            const int p = nt >> 1;
            const int h = (nt & 1) * 2;
            mma_f16(acc[nt], pah[k16], &vh[p][h]);
            mma_f16(acc[nt], pah[k16], &vl[p][h]);
            mma_f16(acc[nt], pal[k16], &vh[p][h]);
        }
    }

    const int row0 = w * 16 + (lane >> 2);
    #pragma unroll
    for (int nt = 0; nt < 8; ++nt) {
        const int col = nt * 8 + tg * 2;
        __half2 v0 = __floats2half2_rn(acc[nt][0], acc[nt][1]);
        __half2 v1 = __floats2half2_rn(acc[nt][2], acc[nt][3]);
        *(__half2*)&mh[(size_t)(b * 64 + row0) * DFEAT + s * 64 + col] = v0;
        *(__half2*)&mh[(size_t)(b * 64 + row0 + 8) * DFEAT + s * 64 + col] = v1;
    }
}

extern "C" void kernel_launch(void* const* d_in, const int* in_sizes, int n_in,
                              void* d_out, int out_size) {
    const float* x  = (const float*)d_in[0];
    const float* Wq = (const float*)d_in[1];
    const float* bq = (const float*)d_in[2];
    const float* Wk = (const float*)d_in[3];
    const float* bk = (const float*)d_in[4];
    const float* Wv = (const float*)d_in[5];
    const float* bv = (const float*)d_in[6];
    const float* Wp = (const float*)d_in[7];
    const float* bp = (const float*)d_in[8];
    float* out = (float*)d_out;

    float* qkv = nullptr;
    __half *xh, *wh, *mh;
    cudaGetSymbolAddress((void**)&qkv, g_qkv);
    cudaGetSymbolAddress((void**)&xh, g_xh);
    cudaGetSymbolAddress((void**)&wh, g_wh);
    cudaGetSymbolAddress((void**)&mh, g_mh);

    cudaFuncSetAttribute(gemm_hmma, cudaFuncAttributeMaxDynamicSharedMemorySize, SMEM_BYTES);

    const size_t MSZ = (size_t)DFEAT * DFEAT;
    const int n4 = (int)(MSZ / 4);

    // 0) fused casts: x + 4 weights
    CastArgs ca;
    ca.src[0] = x;  ca.dst[0] = xh;
    ca.src[1] = Wq; ca.dst[1] = wh;
    ca.src[2] = Wk; ca.dst[2] = wh + MSZ;
    ca.src[3] = Wv; ca.dst[3] = wh + 2 * MSZ;
    ca.src[4] = Wp; ca.dst[4] = wh + 3 * MSZ;
    cast5_kernel<<<dim3(512, 1, 5), 256>>>(ca, n4);

    // 1) QKV projections
    GArgs a1;
    a1.A = xh;
    a1.B[0] = wh;
    a1.B[1] = wh + MSZ;
    a1.B[2] = wh + 2 * MSZ;
    a1.bias[0] = bq; a1.bias[1] = bk; a1.bias[2] = bv;
    a1.C[0] = qkv;
    a1.C[1] = qkv + (size_t)NTOK * DFEAT;
    a1.C[2] = qkv + 2ull * NTOK * DFEAT;
    gemm_hmma<<<dim3(32, 32, 3), 384, SMEM_BYTES>>>(a1);

    // 2) per-token attention -> merged (fp16), tensor-core path
    attn_hmma<<<NTOK, 128>>>(qkv, mh);

    // 3) output projection
    GArgs a2;
    a2.A = mh;
    a2.B[0] = wh + 3 * MSZ;
    a2.B[1] = a2.B[0];
    a2.B[2] = a2.B[0];
    a2.bias[0] = bp; a2.bias[1] = bp; a2.bias[2] = bp;
    a2.C[0] = out; a2.C[1] = out; a2.C[2] = out;
    gemm_hmma<<<dim3(32, 32, 1), 384, SMEM_BYTES>>>(a2);
}